// round 1
// baseline (speedup 1.0000x reference)
#include <cuda_runtime.h>
#include <cstdint>

// Problem constants
static constexpr int B = 8, S = 2048, D = 1024, H = 64;
static constexpr int M = B * S;          // 16384 rows
#define NEG_INF (-1e30f)

// Scratch for projected q (pre-scaled by 1/sqrt(H)), k, v.  [M, H] row-major.
__device__ float g_q[M * H];
__device__ float g_k[M * H];
__device__ float g_v[M * H];

// ---------------------------------------------------------------------------
// Kernel 1: fused QKV projection.  grid = (M/64, 3), block = 256.
// Each block computes a 64x64 output tile (full H) of one of q/k/v.
// q gets the 1/sqrt(64) softmax scale baked in (bias included — correct since
// scores/8 == (q/8)·k elementwise).
// ---------------------------------------------------------------------------
__global__ __launch_bounds__(256) void proj_kernel(
    const float* __restrict__ x,
    const float* __restrict__ Wq, const float* __restrict__ bq,
    const float* __restrict__ Wk, const float* __restrict__ bk,
    const float* __restrict__ Wv, const float* __restrict__ bv)
{
    __shared__ float Xs[64][33];   // +1 pad: conflict-free strided writes
    __shared__ float Ws[32][64];   // row = k, col = h (float4-readable)

    const float* W; const float* bias; float* out; float scale;
    if (blockIdx.y == 0)      { W = Wq; bias = bq; out = g_q; scale = 0.125f; }
    else if (blockIdx.y == 1) { W = Wk; bias = bk; out = g_k; scale = 1.0f; }
    else                      { W = Wv; bias = bv; out = g_v; scale = 1.0f; }

    const int tid = threadIdx.x;
    const int ty = tid >> 4;       // 0..15: row group
    const int tx = tid & 15;       // 0..15: col group
    const int row0 = blockIdx.x * 64;

    float acc[4][4] = {};

    for (int k0 = 0; k0 < D; k0 += 32) {
        // Load 64x32 x-tile (coalesced 32-float rows)
        #pragma unroll
        for (int i = 0; i < 8; i++) {
            int idx = tid + i * 256;
            int r = idx >> 5, kk = idx & 31;
            Xs[r][kk] = x[(size_t)(row0 + r) * D + (k0 + kk)];
        }
        // Load 32x64 W-tile (coalesced 64-float rows)
        #pragma unroll
        for (int i = 0; i < 8; i++) {
            int idx = tid + i * 256;
            int kk = idx >> 6, c = idx & 63;
            Ws[kk][c] = W[(size_t)(k0 + kk) * H + c];
        }
        __syncthreads();

        #pragma unroll
        for (int kk = 0; kk < 32; kk++) {
            float4 wv = *(const float4*)&Ws[kk][tx * 4];
            float a0 = Xs[ty * 4 + 0][kk];
            float a1 = Xs[ty * 4 + 1][kk];
            float a2 = Xs[ty * 4 + 2][kk];
            float a3 = Xs[ty * 4 + 3][kk];
            acc[0][0] += a0 * wv.x; acc[0][1] += a0 * wv.y; acc[0][2] += a0 * wv.z; acc[0][3] += a0 * wv.w;
            acc[1][0] += a1 * wv.x; acc[1][1] += a1 * wv.y; acc[1][2] += a1 * wv.z; acc[1][3] += a1 * wv.w;
            acc[2][0] += a2 * wv.x; acc[2][1] += a2 * wv.y; acc[2][2] += a2 * wv.z; acc[2][3] += a2 * wv.w;
            acc[3][0] += a3 * wv.x; acc[3][1] += a3 * wv.y; acc[3][2] += a3 * wv.z; acc[3][3] += a3 * wv.w;
        }
        __syncthreads();
    }

    #pragma unroll
    for (int i = 0; i < 4; i++) {
        int r = row0 + ty * 4 + i;
        #pragma unroll
        for (int j = 0; j < 4; j++) {
            int c = tx * 4 + j;
            out[(size_t)r * H + c] = (acc[i][j] + bias[c]) * scale;
        }
    }
}

// ---------------------------------------------------------------------------
// Kernel 2: fused causal flash attention. grid = (S/64, B), block = 256.
// One block owns a 64-row Q tile; iterates KV tiles 0..qt with online softmax.
// ---------------------------------------------------------------------------
static constexpr int SMEM_FLOATS = 64 * 64   // Qs
                                 + 64 * 65   // Ks (padded)
                                 + 64 * 64   // Vs
                                 + 64 * 64;  // Ps
static constexpr int SMEM_BYTES = SMEM_FLOATS * 4;  // 65792

__global__ __launch_bounds__(256) void attn_kernel(float* __restrict__ out)
{
    extern __shared__ float sm[];
    float* Qs = sm;                    // [64][64]
    float* Ks = Qs + 64 * 64;          // [64][65]
    float* Vs = Ks + 64 * 65;          // [64][64]
    float* Ps = Vs + 64 * 64;          // [64][64]

    const int tid = threadIdx.x;
    const int ty = tid >> 4;           // row group (0..15)
    const int tx = tid & 15;           // col group (0..15)
    const int qt = blockIdx.x;
    const int bz = blockIdx.y;

    // Load Q tile (already scaled by 1/8)
    const float* qptr = g_q + ((size_t)bz * S + qt * 64) * H;
    #pragma unroll
    for (int i = 0; i < 16; i++) {
        int idx = tid + i * 256;
        Qs[idx] = qptr[idx];
    }

    float m[4], l[4], o[4][4];
    #pragma unroll
    for (int i = 0; i < 4; i++) {
        m[i] = NEG_INF; l[i] = 0.f;
        #pragma unroll
        for (int j = 0; j < 4; j++) o[i][j] = 0.f;
    }

    for (int kt = 0; kt <= qt; kt++) {
        const float* kptr = g_k + ((size_t)bz * S + kt * 64) * H;
        const float* vptr = g_v + ((size_t)bz * S + kt * 64) * H;
        #pragma unroll
        for (int i = 0; i < 16; i++) {
            int idx = tid + i * 256;
            int r = idx >> 6, c = idx & 63;
            Ks[r * 65 + c] = kptr[idx];
            Vs[idx]        = vptr[idx];
        }
        __syncthreads();

        // S = Q @ K^T  (64x64 tile, per-thread 4x4)
        float s[4][4] = {};
        #pragma unroll 8
        for (int d = 0; d < 64; d++) {
            float a0 = Qs[(ty * 4 + 0) * 64 + d];
            float a1 = Qs[(ty * 4 + 1) * 64 + d];
            float a2 = Qs[(ty * 4 + 2) * 64 + d];
            float a3 = Qs[(ty * 4 + 3) * 64 + d];
            float b0 = Ks[(tx * 4 + 0) * 65 + d];
            float b1 = Ks[(tx * 4 + 1) * 65 + d];
            float b2 = Ks[(tx * 4 + 2) * 65 + d];
            float b3 = Ks[(tx * 4 + 3) * 65 + d];
            s[0][0] += a0 * b0; s[0][1] += a0 * b1; s[0][2] += a0 * b2; s[0][3] += a0 * b3;
            s[1][0] += a1 * b0; s[1][1] += a1 * b1; s[1][2] += a1 * b2; s[1][3] += a1 * b3;
            s[2][0] += a2 * b0; s[2][1] += a2 * b1; s[2][2] += a2 * b2; s[2][3] += a2 * b3;
            s[3][0] += a3 * b0; s[3][1] += a3 * b1; s[3][2] += a3 * b2; s[3][3] += a3 * b3;
        }

        // Causal mask applies only on the diagonal tile
        if (kt == qt) {
            #pragma unroll
            for (int i = 0; i < 4; i++)
                #pragma unroll
                for (int j = 0; j < 4; j++)
                    if (tx * 4 + j > ty * 4 + i) s[i][j] = NEG_INF;
        }

        // Online softmax (row reductions across the 16 tx lanes)
        #pragma unroll
        for (int i = 0; i < 4; i++) {
            float t = fmaxf(fmaxf(s[i][0], s[i][1]), fmaxf(s[i][2], s[i][3]));
            #pragma unroll
            for (int off = 1; off < 16; off <<= 1)
                t = fmaxf(t, __shfl_xor_sync(0xffffffffu, t, off));
            float mn = fmaxf(m[i], t);
            float alpha = __expf(m[i] - mn);
            float rs = 0.f;
            #pragma unroll
            for (int j = 0; j < 4; j++) {
                s[i][j] = __expf(s[i][j] - mn);
                rs += s[i][j];
            }
            #pragma unroll
            for (int off = 1; off < 16; off <<= 1)
                rs += __shfl_xor_sync(0xffffffffu, rs, off);
            l[i] = l[i] * alpha + rs;
            m[i] = mn;
            #pragma unroll
            for (int j = 0; j < 4; j++) o[i][j] *= alpha;
            *(float4*)&Ps[(ty * 4 + i) * 64 + tx * 4] =
                make_float4(s[i][0], s[i][1], s[i][2], s[i][3]);
        }
        __syncthreads();

        // O += P @ V
        #pragma unroll 8
        for (int n = 0; n < 64; n++) {
            float4 v4 = *(const float4*)&Vs[n * 64 + tx * 4];
            float p0 = Ps[(ty * 4 + 0) * 64 + n];
            float p1 = Ps[(ty * 4 + 1) * 64 + n];
            float p2 = Ps[(ty * 4 + 2) * 64 + n];
            float p3 = Ps[(ty * 4 + 3) * 64 + n];
            o[0][0] += p0 * v4.x; o[0][1] += p0 * v4.y; o[0][2] += p0 * v4.z; o[0][3] += p0 * v4.w;
            o[1][0] += p1 * v4.x; o[1][1] += p1 * v4.y; o[1][2] += p1 * v4.z; o[1][3] += p1 * v4.w;
            o[2][0] += p2 * v4.x; o[2][1] += p2 * v4.y; o[2][2] += p2 * v4.z; o[2][3] += p2 * v4.w;
            o[3][0] += p3 * v4.x; o[3][1] += p3 * v4.y; o[3][2] += p3 * v4.z; o[3][3] += p3 * v4.w;
        }
        __syncthreads();
    }

    // Normalize and write out
    float* op = out + ((size_t)bz * S + qt * 64) * H;
    #pragma unroll
    for (int i = 0; i < 4; i++) {
        float inv = 1.0f / l[i];
        #pragma unroll
        for (int j = 0; j < 4; j++)
            op[(size_t)(ty * 4 + i) * H + tx * 4 + j] = o[i][j] * inv;
    }
}

// ---------------------------------------------------------------------------
extern "C" void kernel_launch(void* const* d_in, const int* in_sizes, int n_in,
                              void* d_out, int out_size)
{
    const float* x  = (const float*)d_in[0];
    const float* Wq = (const float*)d_in[1];
    const float* bq = (const float*)d_in[2];
    const float* Wk = (const float*)d_in[3];
    const float* bk = (const float*)d_in[4];
    const float* Wv = (const float*)d_in[5];
    const float* bv = (const float*)d_in[6];

    proj_kernel<<<dim3(M / 64, 3), 256>>>(x, Wq, bq, Wk, bk, Wv, bv);

    cudaFuncSetAttribute(attn_kernel,
                         cudaFuncAttributeMaxDynamicSharedMemorySize, SMEM_BYTES);
    attn_kernel<<<dim3(S / 64, B), 256, SMEM_BYTES>>>((float*)d_out);
}

// round 13
// speedup vs baseline: 1.7756x; 1.7756x over previous
#include <cuda_runtime.h>
#include <cuda_bf16.h>
#include <cstdint>

// Problem constants
static constexpr int B = 8, S = 2048, D = 1024, H = 64;
static constexpr int M = B * S;          // 16384 rows
#define NEG_INF (-1e30f)

// Scratch: projected q (pre-scaled by 1/8), k, v  [M, H] fp32.
__device__ float g_q[M * H];
__device__ float g_k[M * H];
__device__ float g_v[M * H];
// Transposed bf16 hi/lo weights: [3][H][D]  (row = output col h, col = d)
__device__ __nv_bfloat16 g_wt_hi[3 * H * D];
__device__ __nv_bfloat16 g_wt_lo[3 * H * D];

// ---------------------------------------------------------------------------
// Warp-MMA helpers (compute_103-safe: sm_80 mma.sync + ldmatrix, NO tcgen05)
// ---------------------------------------------------------------------------
__device__ __forceinline__ uint32_t smem_u32(const void* p) {
    uint32_t a;
    asm("{ .reg .u64 t; cvta.to.shared.u64 t, %1; cvt.u32.u64 %0, t; }"
        : "=r"(a) : "l"(p));
    return a;
}

__device__ __forceinline__ void ldsm_x4(uint32_t* r, uint32_t addr) {
    asm volatile("ldmatrix.sync.aligned.m8n8.x4.shared.b16 {%0,%1,%2,%3}, [%4];"
                 : "=r"(r[0]), "=r"(r[1]), "=r"(r[2]), "=r"(r[3])
                 : "r"(addr));
}

// D = A(16x16 row-major bf16) @ B(16x8, col-major bf16) + D, fp32 accum
__device__ __forceinline__ void mma_bf16(float* c, const uint32_t* a,
                                         uint32_t b0, uint32_t b1) {
    asm volatile(
        "mma.sync.aligned.m16n8k16.row.col.f32.bf16.bf16.f32 "
        "{%0,%1,%2,%3}, {%4,%5,%6,%7}, {%8,%9}, {%0,%1,%2,%3};"
        : "+f"(c[0]), "+f"(c[1]), "+f"(c[2]), "+f"(c[3])
        : "r"(a[0]), "r"(a[1]), "r"(a[2]), "r"(a[3]), "r"(b0), "r"(b1));
}

__device__ __forceinline__ uint32_t pack2(__nv_bfloat16 a, __nv_bfloat16 b) {
    __nv_bfloat162 t; t.x = a; t.y = b;
    return *reinterpret_cast<uint32_t*>(&t);
}

// ---------------------------------------------------------------------------
// Kernel 0: transpose+split weights -> g_wt_hi/lo [w][h][d] bf16
// ---------------------------------------------------------------------------
__global__ void prep_w_kernel(const float* __restrict__ Wq,
                              const float* __restrict__ Wk,
                              const float* __restrict__ Wv)
{
    int idx = blockIdx.x * 256 + threadIdx.x;
    if (idx >= 3 * D * H) return;
    int w = idx / (D * H);
    int r = idx % (D * H);
    int d = r / H, h = r % H;
    const float* W = (w == 0) ? Wq : (w == 1) ? Wk : Wv;
    float v = W[(size_t)d * H + h];
    __nv_bfloat16 hi = __float2bfloat16_rn(v);
    float lo = v - __bfloat162float(hi);
    size_t o = ((size_t)w * H + h) * D + d;
    g_wt_hi[o] = hi;
    g_wt_lo[o] = __float2bfloat16_rn(lo);
}

// ---------------------------------------------------------------------------
// Kernel 1: QKV projection via mma.sync bf16, hi/lo split (hh + hl + lh).
// grid = (M/128, 3), block = 256 (8 warps as 4M x 2N, warp tile 32x32).
// Smem tiles padded to 72 bf16 (144 B) row stride: ldmatrix conflict-free.
// ---------------------------------------------------------------------------
static constexpr int PSTR = 72;                       // padded row stride (bf16)
static constexpr int SM_AHI = 0;                      // [128][72] bf16
static constexpr int SM_ALO = SM_AHI + 128 * PSTR * 2;
static constexpr int SM_BHI = SM_ALO + 128 * PSTR * 2;  // [64][72] bf16
static constexpr int SM_BLO = SM_BHI + 64 * PSTR * 2;
static constexpr int PROJ_SMEM = SM_BLO + 64 * PSTR * 2;  // 55296 B

__global__ __launch_bounds__(256) void proj_mma_kernel(
    const float* __restrict__ x,
    const float* __restrict__ bq, const float* __restrict__ bk,
    const float* __restrict__ bv)
{
    extern __shared__ char sm[];
    const uint32_t sb = smem_u32(sm);

    const int tid = threadIdx.x;
    const int wid = tid >> 5, lane = tid & 31;
    const int wm = wid >> 1;          // 0..3 (M)
    const int wn = wid & 1;           // 0..1 (N)
    const int m0 = blockIdx.x * 128;
    const int wsel = blockIdx.y;      // 0=q, 1=k, 2=v

    const __nv_bfloat16* WH = g_wt_hi + (size_t)wsel * H * D;
    const __nv_bfloat16* WL = g_wt_lo + (size_t)wsel * H * D;

    // ldmatrix lane addressing (shared by A and B tiles)
    const int lrow = lane & 15;
    const int lkb  = (lane >> 4) * 16;   // byte offset for k8-15 half

    float acc[2][4][4] = {};             // [mTile][nTile][c0..c3]

    for (int c = 0; c < D / 64; c++) {
        const int k0 = c * 64;
        __syncthreads();

        // ---- stage A: x fp32 -> hi/lo bf16, padded smem ----
        #pragma unroll
        for (int i = 0; i < 8; i++) {
            int idx = tid + i * 256;          // 2048 float4
            int r = idx >> 4, c4 = idx & 15;
            float4 v = *(const float4*)(x + (size_t)(m0 + r) * D + k0 + c4 * 4);
            __nv_bfloat16 h0 = __float2bfloat16_rn(v.x);
            __nv_bfloat16 h1 = __float2bfloat16_rn(v.y);
            __nv_bfloat16 h2 = __float2bfloat16_rn(v.z);
            __nv_bfloat16 h3 = __float2bfloat16_rn(v.w);
            uint32_t off = (uint32_t)(r * PSTR + c4 * 4) * 2;
            *(uint2*)(sm + SM_AHI + off) = make_uint2(pack2(h0, h1), pack2(h2, h3));
            __nv_bfloat16 l0 = __float2bfloat16_rn(v.x - __bfloat162float(h0));
            __nv_bfloat16 l1 = __float2bfloat16_rn(v.y - __bfloat162float(h1));
            __nv_bfloat16 l2 = __float2bfloat16_rn(v.z - __bfloat162float(h2));
            __nv_bfloat16 l3 = __float2bfloat16_rn(v.w - __bfloat162float(h3));
            *(uint2*)(sm + SM_ALO + off) = make_uint2(pack2(l0, l1), pack2(l2, l3));
        }
        // ---- stage B: weights already bf16 ----
        #pragma unroll
        for (int i = 0; i < 4; i++) {
            int idx = tid + i * 256;          // 1024 uint2 (4 bf16 each)
            int r = idx >> 4, c4 = idx & 15;
            uint32_t off = (uint32_t)(r * PSTR + c4 * 4) * 2;
            *(uint2*)(sm + SM_BHI + off) = *(const uint2*)(WH + (size_t)r * D + k0 + c4 * 4);
            *(uint2*)(sm + SM_BLO + off) = *(const uint2*)(WL + (size_t)r * D + k0 + c4 * 4);
        }
        __syncthreads();

        // ---- MMA over 4 k16-steps ----
        #pragma unroll
        for (int ks = 0; ks < 4; ks++) {
            const uint32_t kb = ks * 32 + lkb;   // byte offset within row
            uint32_t ah[2][4], al[2][4], bh[8], bl[8];
            #pragma unroll
            for (int mt = 0; mt < 2; mt++) {
                uint32_t ra = (uint32_t)((wm * 32 + mt * 16 + lrow) * PSTR * 2) + kb;
                ldsm_x4(ah[mt], sb + SM_AHI + ra);
                ldsm_x4(al[mt], sb + SM_ALO + ra);
            }
            #pragma unroll
            for (int half = 0; half < 2; half++) {
                uint32_t rb = (uint32_t)((wn * 32 + half * 16 + lrow) * PSTR * 2) + kb;
                ldsm_x4(bh + half * 4, sb + SM_BHI + rb);
                ldsm_x4(bl + half * 4, sb + SM_BLO + rb);
            }
            #pragma unroll
            for (int mt = 0; mt < 2; mt++) {
                #pragma unroll
                for (int nt = 0; nt < 4; nt++) {
                    const int p = (nt >> 1) * 4 + (nt & 1);
                    mma_bf16(acc[mt][nt], ah[mt], bh[p], bh[p + 2]);   // hi*hi
                    mma_bf16(acc[mt][nt], ah[mt], bl[p], bl[p + 2]);   // hi*lo
                    mma_bf16(acc[mt][nt], al[mt], bh[p], bh[p + 2]);   // lo*hi
                }
            }
        }
    }

    // ---- epilogue: bias + scale -> fp32 global ----
    float* out = (wsel == 0) ? g_q : (wsel == 1) ? g_k : g_v;
    const float* bi = (wsel == 0) ? bq : (wsel == 1) ? bk : bv;
    const float sc = (wsel == 0) ? 0.125f : 1.0f;
    const int g = lane >> 2, tg = lane & 3;
    #pragma unroll
    for (int mt = 0; mt < 2; mt++) {
        #pragma unroll
        for (int nt = 0; nt < 4; nt++) {
            int r = m0 + wm * 32 + mt * 16 + g;
            int col = wn * 32 + nt * 8 + tg * 2;
            float b0 = bi[col], b1 = bi[col + 1];
            float2 o0 = make_float2((acc[mt][nt][0] + b0) * sc,
                                    (acc[mt][nt][1] + b1) * sc);
            float2 o1 = make_float2((acc[mt][nt][2] + b0) * sc,
                                    (acc[mt][nt][3] + b1) * sc);
            *(float2*)(out + (size_t)r * H + col) = o0;
            *(float2*)(out + (size_t)(r + 8) * H + col) = o1;
        }
    }
}

// ---------------------------------------------------------------------------
// Kernel 2: fused causal flash attention with balanced q-tile pairing.
// grid = (16, 8), block = 256.  Block p handles q-tiles {p, 31-p}:
// (p+1) + (32-p) = 33 KV-iters for every block -> one balanced wave.
// ---------------------------------------------------------------------------
static constexpr int SMEM_FLOATS = 64 * 64 + 64 * 65 + 64 * 64 + 64 * 64;
static constexpr int ATTN_SMEM = SMEM_FLOATS * 4;  // 65792

__global__ __launch_bounds__(256) void attn_kernel(float* __restrict__ out)
{
    extern __shared__ float smf[];
    float* Qs = smf;                   // [64][64]
    float* Ks = Qs + 64 * 64;          // [64][65]
    float* Vs = Ks + 64 * 65;          // [64][64]
    float* Ps = Vs + 64 * 64;          // [64][64]

    const int tid = threadIdx.x;
    const int ty = tid >> 4;
    const int tx = tid & 15;
    const int bz = blockIdx.y;

    for (int sel = 0; sel < 2; sel++) {
        const int qt = sel ? (31 - (int)blockIdx.x) : (int)blockIdx.x;
        __syncthreads();   // protect Qs from previous iteration

        const float* qptr = g_q + ((size_t)bz * S + qt * 64) * H;
        #pragma unroll
        for (int i = 0; i < 16; i++) {
            int idx = tid + i * 256;
            Qs[idx] = qptr[idx];
        }

        float m[4], l[4], o[4][4];
        #pragma unroll
        for (int i = 0; i < 4; i++) {
            m[i] = NEG_INF; l[i] = 0.f;
            #pragma unroll
            for (int j = 0; j < 4; j++) o[i][j] = 0.f;
        }

        for (int kt = 0; kt <= qt; kt++) {
            const float* kptr = g_k + ((size_t)bz * S + kt * 64) * H;
            const float* vptr = g_v + ((size_t)bz * S + kt * 64) * H;
            #pragma unroll
            for (int i = 0; i < 16; i++) {
                int idx = tid + i * 256;
                int r = idx >> 6, c = idx & 63;
                Ks[r * 65 + c] = kptr[idx];
                Vs[idx]        = vptr[idx];
            }
            __syncthreads();

            float s[4][4] = {};
            #pragma unroll 8
            for (int d = 0; d < 64; d++) {
                float a0 = Qs[(ty * 4 + 0) * 64 + d];
                float a1 = Qs[(ty * 4 + 1) * 64 + d];
                float a2 = Qs[(ty * 4 + 2) * 64 + d];
                float a3 = Qs[(ty * 4 + 3) * 64 + d];
                float b0 = Ks[(tx * 4 + 0) * 65 + d];
                float b1 = Ks[(tx * 4 + 1) * 65 + d];
                float b2 = Ks[(tx * 4 + 2) * 65 + d];
                float b3 = Ks[(tx * 4 + 3) * 65 + d];
                s[0][0] += a0 * b0; s[0][1] += a0 * b1; s[0][2] += a0 * b2; s[0][3] += a0 * b3;
                s[1][0] += a1 * b0; s[1][1] += a1 * b1; s[1][2] += a1 * b2; s[1][3] += a1 * b3;
                s[2][0] += a2 * b0; s[2][1] += a2 * b1; s[2][2] += a2 * b2; s[2][3] += a2 * b3;
                s[3][0] += a3 * b0; s[3][1] += a3 * b1; s[3][2] += a3 * b2; s[3][3] += a3 * b3;
            }

            if (kt == qt) {
                #pragma unroll
                for (int i = 0; i < 4; i++)
                    #pragma unroll
                    for (int j = 0; j < 4; j++)
                        if (tx * 4 + j > ty * 4 + i) s[i][j] = NEG_INF;
            }

            #pragma unroll
            for (int i = 0; i < 4; i++) {
                float t = fmaxf(fmaxf(s[i][0], s[i][1]), fmaxf(s[i][2], s[i][3]));
                #pragma unroll
                for (int off = 1; off < 16; off <<= 1)
                    t = fmaxf(t, __shfl_xor_sync(0xffffffffu, t, off));
                float mn = fmaxf(m[i], t);
                float alpha = __expf(m[i] - mn);
                float rs = 0.f;
                #pragma unroll
                for (int j = 0; j < 4; j++) {
                    s[i][j] = __expf(s[i][j] - mn);
                    rs += s[i][j];
                }
                #pragma unroll
                for (int off = 1; off < 16; off <<= 1)
                    rs += __shfl_xor_sync(0xffffffffu, rs, off);
                l[i] = l[i] * alpha + rs;
                m[i] = mn;
                #pragma unroll
                for (int j = 0; j < 4; j++) o[i][j] *= alpha;
                *(float4*)&Ps[(ty * 4 + i) * 64 + tx * 4] =
                    make_float4(s[i][0], s[i][1], s[i][2], s[i][3]);
            }
            __syncthreads();

            #pragma unroll 8
            for (int n = 0; n < 64; n++) {
                float4 v4 = *(const float4*)&Vs[n * 64 + tx * 4];
                float p0 = Ps[(ty * 4 + 0) * 64 + n];
                float p1 = Ps[(ty * 4 + 1) * 64 + n];
                float p2 = Ps[(ty * 4 + 2) * 64 + n];
                float p3 = Ps[(ty * 4 + 3) * 64 + n];
                o[0][0] += p0 * v4.x; o[0][1] += p0 * v4.y; o[0][2] += p0 * v4.z; o[0][3] += p0 * v4.w;
                o[1][0] += p1 * v4.x; o[1][1] += p1 * v4.y; o[1][2] += p1 * v4.z; o[1][3] += p1 * v4.w;
                o[2][0] += p2 * v4.x; o[2][1] += p2 * v4.y; o[2][2] += p2 * v4.z; o[2][3] += p2 * v4.w;
                o[3][0] += p3 * v4.x; o[3][1] += p3 * v4.y; o[3][2] += p3 * v4.z; o[3][3] += p3 * v4.w;
            }
            __syncthreads();
        }

        float* op = out + ((size_t)bz * S + qt * 64) * H;
        #pragma unroll
        for (int i = 0; i < 4; i++) {
            float inv = 1.0f / l[i];
            #pragma unroll
            for (int j = 0; j < 4; j++)
                op[(size_t)(ty * 4 + i) * H + tx * 4 + j] = o[i][j] * inv;
        }
    }
}

// ---------------------------------------------------------------------------
extern "C" void kernel_launch(void* const* d_in, const int* in_sizes, int n_in,
                              void* d_out, int out_size)
{
    const float* x  = (const float*)d_in[0];
    const float* Wq = (const float*)d_in[1];
    const float* bq = (const float*)d_in[2];
    const float* Wk = (const float*)d_in[3];
    const float* bk = (const float*)d_in[4];
    const float* Wv = (const float*)d_in[5];
    const float* bv = (const float*)d_in[6];

    prep_w_kernel<<<(3 * D * H + 255) / 256, 256>>>(Wq, Wk, Wv);

    cudaFuncSetAttribute(proj_mma_kernel,
                         cudaFuncAttributeMaxDynamicSharedMemorySize, PROJ_SMEM);
    proj_mma_kernel<<<dim3(M / 128, 3), 256, PROJ_SMEM>>>(x, bq, bk, bv);

    cudaFuncSetAttribute(attn_kernel,
                         cudaFuncAttributeMaxDynamicSharedMemorySize, ATTN_SMEM);
    attn_kernel<<<dim3(16, B), 256, ATTN_SMEM>>>((float*)d_out);
}

// round 14
// speedup vs baseline: 2.7057x; 1.5238x over previous
#include <cuda_runtime.h>
#include <cuda_bf16.h>
#include <cstdint>

// Problem constants
static constexpr int B = 8, S = 2048, D = 1024, H = 64;
static constexpr int M = B * S;          // 16384 rows
#define NEG_INF (-1e30f)

// Scratch (bf16 hi/lo pairs; q pre-scaled by 1/8)
__device__ __nv_bfloat16 g_q_hi[M * H], g_q_lo[M * H];
__device__ __nv_bfloat16 g_k_hi[M * H], g_k_lo[M * H];
__device__ float g_v[M * H];
__device__ __nv_bfloat16 g_vt_hi[H * M], g_vt_lo[H * M];   // V^T [h][m]
// Transposed bf16 hi/lo weights: [3][H][D]
__device__ __nv_bfloat16 g_wt_hi[3 * H * D];
__device__ __nv_bfloat16 g_wt_lo[3 * H * D];

// ---------------------------------------------------------------------------
// Warp-MMA helpers (compute_103-safe: sm_80 mma.sync + ldmatrix)
// ---------------------------------------------------------------------------
__device__ __forceinline__ uint32_t smem_u32(const void* p) {
    uint32_t a;
    asm("{ .reg .u64 t; cvta.to.shared.u64 t, %1; cvt.u32.u64 %0, t; }"
        : "=r"(a) : "l"(p));
    return a;
}

__device__ __forceinline__ void ldsm_x4(uint32_t* r, uint32_t addr) {
    asm volatile("ldmatrix.sync.aligned.m8n8.x4.shared.b16 {%0,%1,%2,%3}, [%4];"
                 : "=r"(r[0]), "=r"(r[1]), "=r"(r[2]), "=r"(r[3])
                 : "r"(addr));
}

__device__ __forceinline__ void mma_bf16(float* c, const uint32_t* a,
                                         uint32_t b0, uint32_t b1) {
    asm volatile(
        "mma.sync.aligned.m16n8k16.row.col.f32.bf16.bf16.f32 "
        "{%0,%1,%2,%3}, {%4,%5,%6,%7}, {%8,%9}, {%0,%1,%2,%3};"
        : "+f"(c[0]), "+f"(c[1]), "+f"(c[2]), "+f"(c[3])
        : "r"(a[0]), "r"(a[1]), "r"(a[2]), "r"(a[3]), "r"(b0), "r"(b1));
}

__device__ __forceinline__ uint32_t pack2(__nv_bfloat16 a, __nv_bfloat16 b) {
    __nv_bfloat162 t; t.x = a; t.y = b;
    return *reinterpret_cast<uint32_t*>(&t);
}

// ---------------------------------------------------------------------------
// Kernel 0: transpose+split weights -> g_wt_hi/lo [w][h][d] bf16
// ---------------------------------------------------------------------------
__global__ void prep_w_kernel(const float* __restrict__ Wq,
                              const float* __restrict__ Wk,
                              const float* __restrict__ Wv)
{
    int idx = blockIdx.x * 256 + threadIdx.x;
    if (idx >= 3 * D * H) return;
    int w = idx / (D * H);
    int r = idx % (D * H);
    int d = r / H, h = r % H;
    const float* W = (w == 0) ? Wq : (w == 1) ? Wk : Wv;
    float v = W[(size_t)d * H + h];
    __nv_bfloat16 hi = __float2bfloat16_rn(v);
    float lo = v - __bfloat162float(hi);
    size_t o = ((size_t)w * H + h) * D + d;
    g_wt_hi[o] = hi;
    g_wt_lo[o] = __float2bfloat16_rn(lo);
}

// ---------------------------------------------------------------------------
// Kernel 1: QKV projection via mma.sync bf16, hi/lo split (hh + hl + lh).
// grid = (M/128, 3), block = 256 (8 warps as 4M x 2N, warp tile 32x32).
// q/k epilogue writes bf16 hi/lo directly; v written fp32 (for transpose).
// ---------------------------------------------------------------------------
static constexpr int PSTR = 72;                       // padded row stride (bf16)
static constexpr int PSTR2 = PSTR * 2;                // bytes
static constexpr int SM_AHI = 0;                      // [128][72] bf16
static constexpr int SM_ALO = SM_AHI + 128 * PSTR2;
static constexpr int SM_BHI = SM_ALO + 128 * PSTR2;   // [64][72] bf16
static constexpr int SM_BLO = SM_BHI + 64 * PSTR2;
static constexpr int PROJ_SMEM = SM_BLO + 64 * PSTR2; // 55296 B

__global__ __launch_bounds__(256) void proj_mma_kernel(
    const float* __restrict__ x,
    const float* __restrict__ bq, const float* __restrict__ bk,
    const float* __restrict__ bv)
{
    extern __shared__ char sm[];
    const uint32_t sb = smem_u32(sm);

    const int tid = threadIdx.x;
    const int wid = tid >> 5, lane = tid & 31;
    const int wm = wid >> 1;          // 0..3 (M)
    const int wn = wid & 1;           // 0..1 (N)
    const int m0 = blockIdx.x * 128;
    const int wsel = blockIdx.y;      // 0=q, 1=k, 2=v

    const __nv_bfloat16* WH = g_wt_hi + (size_t)wsel * H * D;
    const __nv_bfloat16* WL = g_wt_lo + (size_t)wsel * H * D;

    const int lrow = lane & 15;
    const int lkb  = (lane >> 4) * 16;

    float acc[2][4][4] = {};

    for (int c = 0; c < D / 64; c++) {
        const int k0 = c * 64;
        __syncthreads();

        #pragma unroll
        for (int i = 0; i < 8; i++) {
            int idx = tid + i * 256;
            int r = idx >> 4, c4 = idx & 15;
            float4 v = *(const float4*)(x + (size_t)(m0 + r) * D + k0 + c4 * 4);
            __nv_bfloat16 h0 = __float2bfloat16_rn(v.x);
            __nv_bfloat16 h1 = __float2bfloat16_rn(v.y);
            __nv_bfloat16 h2 = __float2bfloat16_rn(v.z);
            __nv_bfloat16 h3 = __float2bfloat16_rn(v.w);
            uint32_t off = (uint32_t)(r * PSTR + c4 * 4) * 2;
            *(uint2*)(sm + SM_AHI + off) = make_uint2(pack2(h0, h1), pack2(h2, h3));
            __nv_bfloat16 l0 = __float2bfloat16_rn(v.x - __bfloat162float(h0));
            __nv_bfloat16 l1 = __float2bfloat16_rn(v.y - __bfloat162float(h1));
            __nv_bfloat16 l2 = __float2bfloat16_rn(v.z - __bfloat162float(h2));
            __nv_bfloat16 l3 = __float2bfloat16_rn(v.w - __bfloat162float(h3));
            *(uint2*)(sm + SM_ALO + off) = make_uint2(pack2(l0, l1), pack2(l2, l3));
        }
        #pragma unroll
        for (int i = 0; i < 4; i++) {
            int idx = tid + i * 256;
            int r = idx >> 4, c4 = idx & 15;
            uint32_t off = (uint32_t)(r * PSTR + c4 * 4) * 2;
            *(uint2*)(sm + SM_BHI + off) = *(const uint2*)(WH + (size_t)r * D + k0 + c4 * 4);
            *(uint2*)(sm + SM_BLO + off) = *(const uint2*)(WL + (size_t)r * D + k0 + c4 * 4);
        }
        __syncthreads();

        #pragma unroll
        for (int ks = 0; ks < 4; ks++) {
            const uint32_t kb = ks * 32 + lkb;
            uint32_t ah[2][4], al[2][4], bh[8], bl[8];
            #pragma unroll
            for (int mt = 0; mt < 2; mt++) {
                uint32_t ra = (uint32_t)((wm * 32 + mt * 16 + lrow) * PSTR2) + kb;
                ldsm_x4(ah[mt], sb + SM_AHI + ra);
                ldsm_x4(al[mt], sb + SM_ALO + ra);
            }
            #pragma unroll
            for (int half = 0; half < 2; half++) {
                uint32_t rb = (uint32_t)((wn * 32 + half * 16 + lrow) * PSTR2) + kb;
                ldsm_x4(bh + half * 4, sb + SM_BHI + rb);
                ldsm_x4(bl + half * 4, sb + SM_BLO + rb);
            }
            #pragma unroll
            for (int mt = 0; mt < 2; mt++) {
                #pragma unroll
                for (int nt = 0; nt < 4; nt++) {
                    const int p = (nt >> 1) * 4 + (nt & 1);
                    mma_bf16(acc[mt][nt], ah[mt], bh[p], bh[p + 2]);   // hi*hi
                    mma_bf16(acc[mt][nt], ah[mt], bl[p], bl[p + 2]);   // hi*lo
                    mma_bf16(acc[mt][nt], al[mt], bh[p], bh[p + 2]);   // lo*hi
                }
            }
        }
    }

    // ---- epilogue ----
    const int g = lane >> 2, tg = lane & 3;
    if (wsel < 2) {
        __nv_bfloat16* oh = wsel ? g_k_hi : g_q_hi;
        __nv_bfloat16* ol = wsel ? g_k_lo : g_q_lo;
        const float* bi = wsel ? bk : bq;
        const float sc = wsel ? 1.0f : 0.125f;
        #pragma unroll
        for (int mt = 0; mt < 2; mt++) {
            #pragma unroll
            for (int nt = 0; nt < 4; nt++) {
                int r = m0 + wm * 32 + mt * 16 + g;
                int col = wn * 32 + nt * 8 + tg * 2;
                float b0 = bi[col], b1 = bi[col + 1];
                float p0 = (acc[mt][nt][0] + b0) * sc;
                float p1 = (acc[mt][nt][1] + b1) * sc;
                float p2 = (acc[mt][nt][2] + b0) * sc;
                float p3 = (acc[mt][nt][3] + b1) * sc;
                __nv_bfloat16 h0 = __float2bfloat16_rn(p0);
                __nv_bfloat16 h1 = __float2bfloat16_rn(p1);
                __nv_bfloat16 h2 = __float2bfloat16_rn(p2);
                __nv_bfloat16 h3 = __float2bfloat16_rn(p3);
                *(uint32_t*)(oh + (size_t)r * H + col) = pack2(h0, h1);
                *(uint32_t*)(ol + (size_t)r * H + col) =
                    pack2(__float2bfloat16_rn(p0 - __bfloat162float(h0)),
                          __float2bfloat16_rn(p1 - __bfloat162float(h1)));
                *(uint32_t*)(oh + (size_t)(r + 8) * H + col) = pack2(h2, h3);
                *(uint32_t*)(ol + (size_t)(r + 8) * H + col) =
                    pack2(__float2bfloat16_rn(p2 - __bfloat162float(h2)),
                          __float2bfloat16_rn(p3 - __bfloat162float(h3)));
            }
        }
    } else {
        #pragma unroll
        for (int mt = 0; mt < 2; mt++) {
            #pragma unroll
            for (int nt = 0; nt < 4; nt++) {
                int r = m0 + wm * 32 + mt * 16 + g;
                int col = wn * 32 + nt * 8 + tg * 2;
                float b0 = bv[col], b1 = bv[col + 1];
                *(float2*)(g_v + (size_t)r * H + col) =
                    make_float2(acc[mt][nt][0] + b0, acc[mt][nt][1] + b1);
                *(float2*)(g_v + (size_t)(r + 8) * H + col) =
                    make_float2(acc[mt][nt][2] + b0, acc[mt][nt][3] + b1);
            }
        }
    }
}

// ---------------------------------------------------------------------------
// Kernel 1b: V -> V^T hi/lo bf16.  grid = M/64, block = 256.
// ---------------------------------------------------------------------------
__global__ __launch_bounds__(256) void vt_kernel()
{
    __shared__ float t[64][65];
    const int tid = threadIdx.x;
    const int m0 = blockIdx.x * 64;
    #pragma unroll
    for (int i = 0; i < 16; i++) {
        int idx = tid + i * 256;
        int r = idx >> 6, c = idx & 63;
        t[r][c] = g_v[(size_t)(m0 + r) * H + c];
    }
    __syncthreads();
    #pragma unroll
    for (int i = 0; i < 16; i++) {
        int idx = tid + i * 256;
        int h = idx >> 6, mi = idx & 63;
        float v = t[mi][h];
        __nv_bfloat16 hi = __float2bfloat16_rn(v);
        g_vt_hi[(size_t)h * M + m0 + mi] = hi;
        g_vt_lo[(size_t)h * M + m0 + mi] =
            __float2bfloat16_rn(v - __bfloat162float(hi));
    }
}

// ---------------------------------------------------------------------------
// Kernel 2: causal flash attention on mma.sync bf16 (hi/lo, 3 terms/GEMM).
// grid = (16, B), block = 128 (4 warps, warp = 16 q-rows x full 64 cols).
// Block p handles q-tiles {p, 31-p}: 33 KV-iters for every block.
// ---------------------------------------------------------------------------
static constexpr int AT_QH = 0;                       // [64][72]
static constexpr int AT_QL = AT_QH + 64 * PSTR2;
static constexpr int AT_KH = AT_QL + 64 * PSTR2;
static constexpr int AT_KL = AT_KH + 64 * PSTR2;
static constexpr int AT_VH = AT_KL + 64 * PSTR2;
static constexpr int AT_VL = AT_VH + 64 * PSTR2;
static constexpr int ATTN_SMEM = AT_VL + 64 * PSTR2;  // 55296 B

__global__ __launch_bounds__(128) void attn_mma_kernel(float* __restrict__ out)
{
    extern __shared__ char sm[];
    const uint32_t sb = smem_u32(sm);

    const int tid = threadIdx.x;
    const int w = tid >> 5, lane = tid & 31;
    const int g = lane >> 2, tg = lane & 3;
    const int lrow = lane & 15;
    const int lkb  = (lane >> 4) * 16;
    const int bz = blockIdx.y;

    for (int sel = 0; sel < 2; sel++) {
        const int qt = sel ? (31 - (int)blockIdx.x) : (int)blockIdx.x;
        __syncthreads();

        // ---- stage Q tile (64 rows) ----
        const __nv_bfloat16* qh = g_q_hi + ((size_t)bz * S + qt * 64) * H;
        const __nv_bfloat16* ql = g_q_lo + ((size_t)bz * S + qt * 64) * H;
        #pragma unroll
        for (int i = 0; i < 4; i++) {
            int idx = tid + i * 128;
            int r = idx >> 3, c8 = idx & 7;
            *(uint4*)(sm + AT_QH + r * PSTR2 + c8 * 16) =
                *(const uint4*)(qh + (size_t)r * H + c8 * 8);
            *(uint4*)(sm + AT_QL + r * PSTR2 + c8 * 16) =
                *(const uint4*)(ql + (size_t)r * H + c8 * 8);
        }
        __syncthreads();

        // Q fragments held in registers across all KV iterations
        uint32_t aH[4][4], aL[4][4];
        #pragma unroll
        for (int ks = 0; ks < 4; ks++) {
            uint32_t ra = (uint32_t)((w * 16 + lrow) * PSTR2) + ks * 32 + lkb;
            ldsm_x4(aH[ks], sb + AT_QH + ra);
            ldsm_x4(aL[ks], sb + AT_QL + ra);
        }

        float m0 = NEG_INF, m1 = NEG_INF, l0 = 0.f, l1 = 0.f;
        float o[8][4] = {};

        for (int kt = 0; kt <= qt; kt++) {
            __syncthreads();   // previous iteration's ldsm reads complete
            // ---- stage K (row-major) and V^T (h-major) hi/lo tiles ----
            const __nv_bfloat16* kh = g_k_hi + ((size_t)bz * S + kt * 64) * H;
            const __nv_bfloat16* kl = g_k_lo + ((size_t)bz * S + kt * 64) * H;
            const size_t vo = (size_t)bz * S + kt * 64;
            #pragma unroll
            for (int i = 0; i < 4; i++) {
                int idx = tid + i * 128;
                int r = idx >> 3, c8 = idx & 7;
                *(uint4*)(sm + AT_KH + r * PSTR2 + c8 * 16) =
                    *(const uint4*)(kh + (size_t)r * H + c8 * 8);
                *(uint4*)(sm + AT_KL + r * PSTR2 + c8 * 16) =
                    *(const uint4*)(kl + (size_t)r * H + c8 * 8);
                *(uint4*)(sm + AT_VH + r * PSTR2 + c8 * 16) =
                    *(const uint4*)(g_vt_hi + (size_t)r * M + vo + c8 * 8);
                *(uint4*)(sm + AT_VL + r * PSTR2 + c8 * 16) =
                    *(const uint4*)(g_vt_lo + (size_t)r * M + vo + c8 * 8);
            }
            __syncthreads();

            // ---- S = Q @ K^T ----
            float s[8][4] = {};
            #pragma unroll
            for (int ks = 0; ks < 4; ks++) {
                const uint32_t kb = ks * 32 + lkb;
                #pragma unroll
                for (int half = 0; half < 4; half++) {
                    uint32_t fh[4], fl[4];
                    uint32_t rb = (uint32_t)((half * 16 + lrow) * PSTR2) + kb;
                    ldsm_x4(fh, sb + AT_KH + rb);
                    ldsm_x4(fl, sb + AT_KL + rb);
                    #pragma unroll
                    for (int j = 0; j < 2; j++) {
                        const int nt = half * 2 + j;
                        mma_bf16(s[nt], aH[ks], fh[j], fh[j + 2]);
                        mma_bf16(s[nt], aH[ks], fl[j], fl[j + 2]);
                        mma_bf16(s[nt], aL[ks], fh[j], fh[j + 2]);
                    }
                }
            }

            // ---- causal mask (diag tile only) ----
            if (kt == qt) {
                const int rb = w * 16 + g;
                #pragma unroll
                for (int nt = 0; nt < 8; nt++) {
                    int c0 = nt * 8 + tg * 2;
                    if (c0 > rb)         s[nt][0] = NEG_INF;
                    if (c0 + 1 > rb)     s[nt][1] = NEG_INF;
                    if (c0 > rb + 8)     s[nt][2] = NEG_INF;
                    if (c0 + 1 > rb + 8) s[nt][3] = NEG_INF;
                }
            }

            // ---- online softmax (rows g and g+8; quad = one row) ----
            float mx0 = NEG_INF, mx1 = NEG_INF;
            #pragma unroll
            for (int nt = 0; nt < 8; nt++) {
                mx0 = fmaxf(mx0, fmaxf(s[nt][0], s[nt][1]));
                mx1 = fmaxf(mx1, fmaxf(s[nt][2], s[nt][3]));
            }
            mx0 = fmaxf(mx0, __shfl_xor_sync(0xffffffffu, mx0, 1));
            mx0 = fmaxf(mx0, __shfl_xor_sync(0xffffffffu, mx0, 2));
            mx1 = fmaxf(mx1, __shfl_xor_sync(0xffffffffu, mx1, 1));
            mx1 = fmaxf(mx1, __shfl_xor_sync(0xffffffffu, mx1, 2));
            float mn0 = fmaxf(m0, mx0), mn1 = fmaxf(m1, mx1);
            float a0 = __expf(m0 - mn0), a1 = __expf(m1 - mn1);
            float rs0 = 0.f, rs1 = 0.f;
            #pragma unroll
            for (int nt = 0; nt < 8; nt++) {
                s[nt][0] = __expf(s[nt][0] - mn0);
                s[nt][1] = __expf(s[nt][1] - mn0);
                s[nt][2] = __expf(s[nt][2] - mn1);
                s[nt][3] = __expf(s[nt][3] - mn1);
                rs0 += s[nt][0] + s[nt][1];
                rs1 += s[nt][2] + s[nt][3];
            }
            rs0 += __shfl_xor_sync(0xffffffffu, rs0, 1);
            rs0 += __shfl_xor_sync(0xffffffffu, rs0, 2);
            rs1 += __shfl_xor_sync(0xffffffffu, rs1, 1);
            rs1 += __shfl_xor_sync(0xffffffffu, rs1, 2);
            l0 = l0 * a0 + rs0; m0 = mn0;
            l1 = l1 * a1 + rs1; m1 = mn1;
            #pragma unroll
            for (int ht = 0; ht < 8; ht++) {
                o[ht][0] *= a0; o[ht][1] *= a0;
                o[ht][2] *= a1; o[ht][3] *= a1;
            }

            // ---- O += P @ V  (P from registers, hi/lo) ----
            #pragma unroll
            for (int ks = 0; ks < 4; ks++) {
                uint32_t ph[4], pl[4];
                #pragma unroll
                for (int half = 0; half < 2; half++) {
                    const float* sv = s[2 * ks + half];
                    __nv_bfloat16 h0 = __float2bfloat16_rn(sv[0]);
                    __nv_bfloat16 h1 = __float2bfloat16_rn(sv[1]);
                    __nv_bfloat16 h2 = __float2bfloat16_rn(sv[2]);
                    __nv_bfloat16 h3 = __float2bfloat16_rn(sv[3]);
                    ph[half * 2 + 0] = pack2(h0, h1);
                    ph[half * 2 + 1] = pack2(h2, h3);
                    pl[half * 2 + 0] =
                        pack2(__float2bfloat16_rn(sv[0] - __bfloat162float(h0)),
                              __float2bfloat16_rn(sv[1] - __bfloat162float(h1)));
                    pl[half * 2 + 1] =
                        pack2(__float2bfloat16_rn(sv[2] - __bfloat162float(h2)),
                              __float2bfloat16_rn(sv[3] - __bfloat162float(h3)));
                }
                // reorder: a-frag wants {(m0-7,k0-7),(m8-15,k0-7),(m0-7,k8-15),(m8-15,k8-15)}
                uint32_t pa[4] = { ph[0], ph[1], ph[2], ph[3] };
                uint32_t pb[4] = { pl[0], pl[1], pl[2], pl[3] };
                const uint32_t kb = ks * 32 + lkb;
                #pragma unroll
                for (int half = 0; half < 4; half++) {
                    uint32_t fh[4], fl[4];
                    uint32_t rb = (uint32_t)((half * 16 + lrow) * PSTR2) + kb;
                    ldsm_x4(fh, sb + AT_VH + rb);
                    ldsm_x4(fl, sb + AT_VL + rb);
                    #pragma unroll
                    for (int j = 0; j < 2; j++) {
                        const int ht = half * 2 + j;
                        mma_bf16(o[ht], pa, fh[j], fh[j + 2]);
                        mma_bf16(o[ht], pa, fl[j], fl[j + 2]);
                        mma_bf16(o[ht], pb, fh[j], fh[j + 2]);
                    }
                }
            }
        }

        // ---- normalize + write ----
        float inv0 = 1.0f / l0, inv1 = 1.0f / l1;
        size_t row = (size_t)bz * S + qt * 64 + w * 16 + g;
        #pragma unroll
        for (int ht = 0; ht < 8; ht++) {
            int col = ht * 8 + tg * 2;
            *(float2*)(out + row * H + col) =
                make_float2(o[ht][0] * inv0, o[ht][1] * inv0);
            *(float2*)(out + (row + 8) * H + col) =
                make_float2(o[ht][2] * inv1, o[ht][3] * inv1);
        }
    }
}

// ---------------------------------------------------------------------------
extern "C" void kernel_launch(void* const* d_in, const int* in_sizes, int n_in,
                              void* d_out, int out_size)
{
    const float* x  = (const float*)d_in[0];
    const float* bq = (const float*)d_in[2];
    const float* bk = (const float*)d_in[4];
    const float* bv = (const float*)d_in[6];
    const float* Wq = (const float*)d_in[1];
    const float* Wk = (const float*)d_in[3];
    const float* Wv = (const float*)d_in[5];

    prep_w_kernel<<<(3 * D * H + 255) / 256, 256>>>(Wq, Wk, Wv);

    cudaFuncSetAttribute(proj_mma_kernel,
                         cudaFuncAttributeMaxDynamicSharedMemorySize, PROJ_SMEM);
    proj_mma_kernel<<<dim3(M / 128, 3), 256, PROJ_SMEM>>>(x, bq, bk, bv);

    vt_kernel<<<M / 64, 256>>>();

    cudaFuncSetAttribute(attn_mma_kernel,
                         cudaFuncAttributeMaxDynamicSharedMemorySize, ATTN_SMEM);
    attn_mma_kernel<<<dim3(16, B), 128, ATTN_SMEM>>>((float*)d_out);
}